// round 4
// baseline (speedup 1.0000x reference)
#include <cuda_runtime.h>
#include <math_constants.h>

#define SDIM 2048
#define BDIM 32
#define HDIM 1024

#define KS 16          // k-splits
#define KT (HDIM / KS) // 64 k per split
#define HT 128         // h per block tile

// Scratch (no device allocs allowed)
__device__ float g_part[KS * BDIM * HDIM];      // split-K partials (2 MB)
__device__ float g_u[BDIM * HDIM];              // u = hidden @ W
__device__ float g_scores[BDIM * SDIM];         // scores[b,s]
__device__ unsigned int g_maxbits[BDIM];        // order-preserving float max per b

// order-preserving float -> uint32 (monotone; unsigned compare == float compare)
__device__ __forceinline__ unsigned int f2mono(float f) {
    unsigned int u = __float_as_uint(f);
    return (u & 0x80000000u) ? ~u : (u | 0x80000000u);
}
__device__ __forceinline__ float mono2f(unsigned int u) {
    return __uint_as_float((u & 0x80000000u) ? (u & 0x7FFFFFFFu) : ~u);
}

// ---------------------------------------------------------------------------
// Kernel 1a: split-K tiled GEMM  u_part = hidden[:, krange] @ W[krange, htile]
// ---------------------------------------------------------------------------
__global__ __launch_bounds__(256) void proj_kernel(
    const float* __restrict__ hidden, const float* __restrict__ W) {
    __shared__ float4 sW[KT * (HT / 4)];   // 32 KB
    __shared__ float  sH[BDIM * KT];       // 8 KB

    const int h0 = blockIdx.x * HT;
    const int k0 = blockIdx.y * KT;
    const int tid = threadIdx.x;

    const float4* __restrict__ Wg = reinterpret_cast<const float4*>(W);
#pragma unroll
    for (int i = 0; i < (KT * HT / 4) / 256; ++i) {
        int idx = tid + i * 256;
        int kk = idx >> 5;
        int c  = idx & 31;
        sW[idx] = Wg[(size_t)(k0 + kk) * (HDIM / 4) + (h0 >> 2) + c];
    }
#pragma unroll
    for (int i = 0; i < (BDIM * KT) / 256; ++i) {
        int idx = tid + i * 256;
        int bb = idx >> 6;
        int kk = idx & 63;
        sH[idx] = hidden[bb * HDIM + k0 + kk];
    }
    __syncthreads();

    const int lane = tid & 31;
    const int b0 = (tid >> 5) * 4;

    float4 acc0 = {0,0,0,0}, acc1 = {0,0,0,0}, acc2 = {0,0,0,0}, acc3 = {0,0,0,0};
#pragma unroll 8
    for (int k = 0; k < KT; ++k) {
        float4 w4 = sW[k * 32 + lane];
        float h0v = sH[(b0 + 0) * KT + k];
        float h1v = sH[(b0 + 1) * KT + k];
        float h2v = sH[(b0 + 2) * KT + k];
        float h3v = sH[(b0 + 3) * KT + k];
        acc0.x = fmaf(h0v, w4.x, acc0.x); acc0.y = fmaf(h0v, w4.y, acc0.y);
        acc0.z = fmaf(h0v, w4.z, acc0.z); acc0.w = fmaf(h0v, w4.w, acc0.w);
        acc1.x = fmaf(h1v, w4.x, acc1.x); acc1.y = fmaf(h1v, w4.y, acc1.y);
        acc1.z = fmaf(h1v, w4.z, acc1.z); acc1.w = fmaf(h1v, w4.w, acc1.w);
        acc2.x = fmaf(h2v, w4.x, acc2.x); acc2.y = fmaf(h2v, w4.y, acc2.y);
        acc2.z = fmaf(h2v, w4.z, acc2.z); acc2.w = fmaf(h2v, w4.w, acc2.w);
        acc3.x = fmaf(h3v, w4.x, acc3.x); acc3.y = fmaf(h3v, w4.y, acc3.y);
        acc3.z = fmaf(h3v, w4.z, acc3.z); acc3.w = fmaf(h3v, w4.w, acc3.w);
    }

    float4* __restrict__ part4 = reinterpret_cast<float4*>(
        g_part + (size_t)blockIdx.y * BDIM * HDIM);
    const int hbase4 = (h0 >> 2) + lane;
    part4[(b0 + 0) * (HDIM / 4) + hbase4] = acc0;
    part4[(b0 + 1) * (HDIM / 4) + hbase4] = acc1;
    part4[(b0 + 2) * (HDIM / 4) + hbase4] = acc2;
    part4[(b0 + 3) * (HDIM / 4) + hbase4] = acc3;
}

// ---------------------------------------------------------------------------
// Kernel 1b: fold split-K partials; also (re)init g_maxbits for this replay.
// ---------------------------------------------------------------------------
__global__ __launch_bounds__(256) void reduce_kernel() {
    const int idx = blockIdx.x * 256 + threadIdx.x;
    if (blockIdx.x == 0 && threadIdx.x < BDIM) g_maxbits[threadIdx.x] = 0u;
    float s = 0.0f;
#pragma unroll
    for (int j = 0; j < KS; ++j) s += g_part[j * (BDIM * HDIM) + idx];
    g_u[idx] = s;
}

// ---------------------------------------------------------------------------
// Kernel 2: scores[b,s] = u[b] . enc[s,b,:]  — HBM-roofline stream of 268 MB.
// Block = (b, 8 consecutive s): warp w handles s = s0 + w, all same b.
// Block-local max -> ONE deterministic atomicMax per block.
// ---------------------------------------------------------------------------
__global__ __launch_bounds__(256) void score_kernel(const float* __restrict__ enc) {
    const int bid = blockIdx.x;
    const int b = bid & (BDIM - 1);
    const int s0 = (bid >> 5) * 8;
    const int w = threadIdx.x >> 5;
    const int lane = threadIdx.x & 31;
    const int s = s0 + w;

    const float4* __restrict__ erow =
        reinterpret_cast<const float4*>(enc + ((size_t)s * BDIM + b) * HDIM);
    const float4* __restrict__ urow =
        reinterpret_cast<const float4*>(g_u + b * HDIM);

    float acc = 0.0f;
#pragma unroll
    for (int j = 0; j < 8; ++j) {
        float4 e = __ldcs(&erow[j * 32 + lane]);   // streaming, evict-first
        float4 u = __ldg(&urow[j * 32 + lane]);    // cached (L1/L2 resident)
        acc = fmaf(e.x, u.x, acc);
        acc = fmaf(e.y, u.y, acc);
        acc = fmaf(e.z, u.z, acc);
        acc = fmaf(e.w, u.w, acc);
    }
#pragma unroll
    for (int off = 16; off > 0; off >>= 1)
        acc += __shfl_xor_sync(0xFFFFFFFFu, acc, off);

    __shared__ float swres[8];
    if (lane == 0) {
        g_scores[b * SDIM + s] = acc;
        swres[w] = acc;
    }
    __syncthreads();
    if (threadIdx.x == 0) {
        float m = swres[0];
#pragma unroll
        for (int j = 1; j < 8; ++j) m = fmaxf(m, swres[j]);
        atomicMax(&g_maxbits[b], f2mono(m));   // deterministic (max is assoc+comm)
    }
}

// ---------------------------------------------------------------------------
// Kernel 3: single-phase softmax: max already known. 32 blocks x 1024 thr.
// ---------------------------------------------------------------------------
__global__ __launch_bounds__(1024) void softmax_kernel(float* __restrict__ out) {
    const int b = blockIdx.x;
    const int tid = threadIdx.x;
    const float* __restrict__ row = g_scores + b * SDIM;

    __shared__ float sred[32];

    const float vmax = mono2f(g_maxbits[b]);
    float v0 = __expf(row[tid] - vmax);
    float v1 = __expf(row[tid + 1024] - vmax);
    float lsum = v0 + v1;
#pragma unroll
    for (int off = 16; off > 0; off >>= 1)
        lsum += __shfl_xor_sync(0xFFFFFFFFu, lsum, off);
    if ((tid & 31) == 0) sred[tid >> 5] = lsum;
    __syncthreads();
    if (tid < 32) {
        float v = sred[tid];
#pragma unroll
        for (int off = 16; off > 0; off >>= 1)
            v += __shfl_xor_sync(0xFFFFFFFFu, v, off);
        sred[0] = v;
    }
    __syncthreads();
    const float inv = 1.0f / sred[0];

    out[b * SDIM + tid]        = v0 * inv;
    out[b * SDIM + tid + 1024] = v1 * inv;
}

// ---------------------------------------------------------------------------
extern "C" void kernel_launch(void* const* d_in, const int* in_sizes, int n_in,
                              void* d_out, int out_size) {
    const float* hidden = (const float*)d_in[0];  // [B,H]
    const float* enc    = (const float*)d_in[1];  // [S,B,H]
    const float* W      = (const float*)d_in[2];  // [H,H]
    float* out = (float*)d_out;                   // [1,B,S]

    dim3 pg(HDIM / HT, KS);                       // (8, 16)
    proj_kernel<<<pg, 256>>>(hidden, W);
    reduce_kernel<<<(BDIM * HDIM) / 256, 256>>>();

    score_kernel<<<BDIM * (SDIM / 8), 256>>>(enc);   // 8192 blocks

    softmax_kernel<<<BDIM, 1024>>>(out);
}